// round 14
// baseline (speedup 1.0000x reference)
#include <cuda_runtime.h>
#include <cuda_bf16.h>
#include <cstdint>

#define SEQ    2048
#define EMB    256
#define HH     256
#define G4     1024      // 4*HH gate rows
#define NTAGS  12
#define TAG_START 10
#define TAG_STOP  11
#define NEGC  (-10000.0f)
#define NCHUNK 128
#define CLEN   (SEQ / NCHUNK)
#define CL     16                  // cluster size (CTAs per direction)
#define EPAD   36                  // padded eighth stride in floats (32 + 4)
#define HBUF8  (8 * EPAD)          // 288 floats per h buffer
#define GPSTRIDE 12                // gate_p row stride in floats (8 partials + 4 pad)

// ---------------- scratch (device globals; no allocation allowed) ----------------
__device__ float g_xbuf[SEQ * EMB];            // gathered embeddings       (2 MB)
__device__ float g_pre [2 * SEQ * G4];         // input projections f/b     (16 MB)
__device__ float g_hs  [2 * SEQ * HH];         // hidden states f/b         (4 MB)
__device__ float g_feats[SEQ * NTAGS];         // emissions
__device__ float g_crfT[NCHUNK][NTAGS][NTAGS]; // per-chunk CRF transfer matrices
__device__ int   g_dummy;

__device__ __forceinline__ uint32_t smem_u32(const void* p) {
    return (uint32_t)__cvta_generic_to_shared(p);
}

__device__ __forceinline__ float htanh(float x) {
    float y;
    asm("tanh.approx.f32 %0, %1;" : "=f"(y) : "f"(x));
    return y;
}
__device__ __forceinline__ float hsigmoid(float x) {
    return fmaf(0.5f, htanh(0.5f * x), 0.5f);
}

__device__ __forceinline__ void fma2(unsigned long long& d,
                                     unsigned long long a, unsigned long long b) {
    asm("fma.rn.f32x2 %0, %1, %2, %0;" : "+l"(d) : "l"(a), "l"(b));
}

__device__ __forceinline__ void mbar_wait_acq(uint32_t mb, uint32_t parity) {
    uint32_t done;
    asm volatile(
        "{\n\t.reg .pred p;\n\t"
        "mbarrier.try_wait.parity.acquire.cluster.shared::cta.b64 p, [%1], %2, 0x989680;\n\t"
        "selp.b32 %0, 1, 0, p;\n\t}"
        : "=r"(done) : "r"(mb), "r"(parity) : "memory");
    while (!done) {
        asm volatile(
            "{\n\t.reg .pred p;\n\t"
            "mbarrier.try_wait.parity.acquire.cluster.shared::cta.b64 p, [%1], %2, 0x989680;\n\t"
            "selp.b32 %0, 1, 0, p;\n\t}"
            : "=r"(done) : "r"(mb), "r"(parity) : "memory");
    }
}

// ---------------- kernel 0: embedding gather ----------------
__global__ void gather_x_kernel(const float* __restrict__ embed,
                                const int* __restrict__ sent) {
    int t = blockIdx.x;
    int k = threadIdx.x;
    long row = (long)sent[t];
    float4 v = reinterpret_cast<const float4*>(embed + row * EMB)[k];
    reinterpret_cast<float4*>(g_xbuf + t * EMB)[k] = v;
}

// ---------------- kernel 1: pre = x @ Wih^T + bih + bhh (128x64 tiles, 8x4/thread) ----------------
__global__ void gemm_pre_kernel(const float* __restrict__ WihF, const float* __restrict__ WihB,
                                const float* __restrict__ bihF, const float* __restrict__ bhhF,
                                const float* __restrict__ bihB, const float* __restrict__ bhhB) {
    const int dir = blockIdx.z;
    const int r0  = blockIdx.x * 128;
    const int t0  = blockIdx.y * 64;
    const float* __restrict__ Wih = dir ? WihB : WihF;
    const float* __restrict__ bih = dir ? bihB : bihF;
    const float* __restrict__ bhh = dir ? bhhB : bhhF;

    __shared__ float Ws[32][128];   // [k][r swizzled by k4]
    __shared__ float Xs[32][68];    // [k][t] (+4 pad)

    const int tid = threadIdx.x;
    const int tx = tid & 15;
    const int ty = tid >> 4;
    float acc[8][4] = {};

    for (int kc = 0; kc < EMB; kc += 32) {
#pragma unroll
        for (int i = 0; i < 4; i++) {
            int s = tid + i * 256;
            int r = s >> 3, k4 = s & 7;
            float4 v = *reinterpret_cast<const float4*>(&Wih[(size_t)(r0 + r) * EMB + kc + k4 * 4]);
            int rs = r ^ (k4 << 3);
            Ws[k4 * 4 + 0][rs] = v.x;
            Ws[k4 * 4 + 1][rs] = v.y;
            Ws[k4 * 4 + 2][rs] = v.z;
            Ws[k4 * 4 + 3][rs] = v.w;
        }
#pragma unroll
        for (int i = 0; i < 2; i++) {
            int s = tid + i * 256;
            int t = s >> 3, k4 = s & 7;
            float4 v = *reinterpret_cast<const float4*>(&g_xbuf[(size_t)(t0 + t) * EMB + kc + k4 * 4]);
            Xs[k4 * 4 + 0][t] = v.x;
            Xs[k4 * 4 + 1][t] = v.y;
            Xs[k4 * 4 + 2][t] = v.z;
            Xs[k4 * 4 + 3][t] = v.w;
        }
        __syncthreads();
#pragma unroll
        for (int k = 0; k < 32; k++) {
            const int k4 = k >> 2;
            const int rbase = ((ty ^ k4) & 15) << 3;
            float4 wv0 = *reinterpret_cast<const float4*>(&Ws[k][rbase]);
            float4 wv1 = *reinterpret_cast<const float4*>(&Ws[k][rbase + 4]);
            float4 xv  = *reinterpret_cast<const float4*>(&Xs[k][tx << 2]);
            float wr[8] = {wv0.x, wv0.y, wv0.z, wv0.w, wv1.x, wv1.y, wv1.z, wv1.w};
            float xc[4] = {xv.x, xv.y, xv.z, xv.w};
#pragma unroll
            for (int i = 0; i < 8; i++)
#pragma unroll
                for (int j = 0; j < 4; j++)
                    acc[i][j] = fmaf(wr[i], xc[j], acc[i][j]);
        }
        __syncthreads();
    }
    float b[8];
#pragma unroll
    for (int i = 0; i < 8; i++) {
        int r = r0 + ty * 8 + i;
        b[i] = bih[r] + bhh[r];
    }
    float* preD = g_pre + (size_t)dir * SEQ * G4;
#pragma unroll
    for (int j = 0; j < 4; j++) {
        int t = t0 + tx * 4 + j;
        float4 v0, v1;
        v0.x = acc[0][j] + b[0];
        v0.y = acc[1][j] + b[1];
        v0.z = acc[2][j] + b[2];
        v0.w = acc[3][j] + b[3];
        v1.x = acc[4][j] + b[4];
        v1.y = acc[5][j] + b[5];
        v1.z = acc[6][j] + b[6];
        v1.w = acc[7][j] + b[7];
        float* dst = preD + (size_t)t * G4 + r0 + ty * 8;
        *reinterpret_cast<float4*>(dst)     = v0;
        *reinterpret_cast<float4*>(dst + 4) = v1;
    }
}

// ---------------- dummy kernel (launch-slot shim so ncu captures the lstm kernel) ----------------
__global__ void dummy_kernel() {
    if (threadIdx.x == 0) g_dummy = 1;
}

// ---------------- kernel 2: LSTM recurrence, 16-CTA cluster, EIGHTH sub-barriers ----------------
// Gemv warps 0-15: warp-uniform eighth ke = w>>1; each thread owns a full 32-wide
// k slice of its gate row -> NO shfl reduction. Each eighth's warps wait only on
// sub-mbar[ke] (expect 128B from the 2 CTAs owning that eighth's h). Partials go
// to gate_p[row][ke] (stride-12 pad: conflict-free STS). Act warps 16/17 sum the
// 8 partials, apply activations, send. bar3 closes the gate_p WAR window: act
// arrives after reading, gemv syncs before writing (skipped at s=0).
__global__ void __launch_bounds__(576, 1) __cluster_dims__(CL, 1, 1)
lstm_rec_kernel(const float* __restrict__ WhhF, const float* __restrict__ WhhB,
                const float* __restrict__ h0, const float* __restrict__ c0) {
    const int tid = threadIdx.x;
    const int w   = tid >> 5;
    const int l   = tid & 31;
    const int crank = blockIdx.x & (CL - 1);   // rank within cluster
    const int dir   = blockIdx.x >> 4;         // 0 = forward, 1 = backward
    const int u0    = crank * 16;              // first hidden unit owned by this CTA

    const float* __restrict__ Whh = dir ? WhhB : WhhF;
    const float* __restrict__ pre = g_pre + (size_t)dir * SEQ * G4;
    float* __restrict__ hs = g_hs + (size_t)dir * SEQ * HH;

    __shared__ __align__(16) float hbuf[2][HBUF8];
    __shared__ __align__(16) float gate_p[64 * GPSTRIDE];   // [row][8 partials + pad]
    __shared__ __align__(16) float stage[2][16];
    __shared__ __align__(8) unsigned long long mbarS[16];   // [ke*2 + buf]

    // init: every CTA loads the FULL initial h locally (eighth-padded layout)
    if (tid < HH) hbuf[0][(tid >> 5) * EPAD + (tid & 31)] = h0[dir * HH + tid];
    const int ubase = (w >= 16) ? (w - 16) * 8 : 0;
    float creg = 0.f;
    if (w >= 16 && l < 8) creg = c0[dir * HH + u0 + ubase + l];

    const uint32_t hbase = smem_u32(&hbuf[0][0]);
    const uint32_t mb0   = smem_u32(&mbarS[0]);
    const uint32_t mbDelta = mb0 - hbase;

    if (tid == 0) {
#pragma unroll
        for (int i = 0; i < 16; i++) {
            uint32_t a = mb0 + i * 8;
            asm volatile("mbarrier.init.shared.b64 [%0], 1;" :: "r"(a) : "memory");
            asm volatile("mbarrier.arrive.expect_tx.shared.b64 _, [%0], 128;" :: "r"(a) : "memory");
        }
    }

    // gemv mapping (warps 0-15): eighth ke = w>>1, row = (w&1)*32 + l (0..63)
    const int ke   = w >> 1;
    const int row  = ((w & 1) << 5) + l;      // local gate row 0..63
    const int gate = row >> 4;
    const int urow = row & 15;
    const int grow = gate * HH + u0 + urow;   // global gate row

    unsigned long long w2[16];
    if (w < 16) {
        const ulonglong2* wr = reinterpret_cast<const ulonglong2*>(Whh + (size_t)grow * HH + ke * 32);
#pragma unroll
        for (int i = 0; i < 8; i++) {
            ulonglong2 v = wr[i];
            w2[2 * i]     = v.x;
            w2[2 * i + 1] = v.y;
        }
    }

    // act/send warp addressing (warps 16,17): lane -> rank l&15, packet
    uint32_t ma0 = 0, ma1 = 0, d0 = 0, d1 = 0;
    int pkt = 0;
    if (w >= 16) {
        int s_rank = l & 15;
        pkt = (w - 16) * 2 + (l >> 4);        // 0..3: 16B packet index of my CTA's slice
        uint32_t pb;
        asm("mapa.shared::cluster.u32 %0, %1, %2;" : "=r"(pb) : "r"(hbase), "r"(s_rank));
        uint32_t dstOff = (uint32_t)(((crank >> 1) * EPAD + (crank & 1) * 16) * 4) + (uint32_t)pkt * 16;
        int e = crank >> 1;                   // which sub-mbar my data feeds
        ma0 = pb + mbDelta + (uint32_t)(e * 2 + 0) * 8;
        ma1 = pb + mbDelta + (uint32_t)(e * 2 + 1) * 8;
        d0  = pb + dstOff;
        d1  = pb + (uint32_t)(HBUF8 * 4) + dstOff;
    }
    __syncthreads();
    // mbarrier inits + phase-0 expects must be cluster-visible before any send
    asm volatile("barrier.cluster.arrive.aligned;" ::: "memory");
    asm volatile("barrier.cluster.wait.aligned;"   ::: "memory");

    if (w < 16) {
        // ================= gemv warps =================
        int pce[2] = {0, 0};
        const bool hasPre   = (ke == 0);
        const bool reposter = ((w & 1) == 0) && (l == 0);
        float pr_cur = 0.f;
        if (hasPre) pr_cur = __ldg(&pre[(size_t)(dir ? (SEQ - 1) : 0) * G4 + grow]);

        for (int s = 0; s < SEQ; s++) {
            const int cur = s & 1;
            float pr_nxt = 0.f;
            if (hasPre && s + 1 < SEQ) {
                int tn = dir ? (SEQ - 2 - s) : (s + 1);
                pr_nxt = __ldg(&pre[(size_t)tn * G4 + grow]);
            }

            if (s > 0) {
                uint32_t parity = (uint32_t)(pce[cur] & 1);
                pce[cur]++;
                uint32_t mb = mb0 + (uint32_t)(ke * 2 + cur) * 8;
                mbar_wait_acq(mb, parity);
                if (reposter)
                    asm volatile("mbarrier.arrive.expect_tx.shared.b64 _, [%0], 128;" :: "r"(mb) : "memory");
            }

            // ---- gemv: full 32-wide eighth per thread (broadcast reads) ----
            const ulonglong2* hp = reinterpret_cast<const ulonglong2*>(&hbuf[cur][ke * EPAD]);
            unsigned long long a0 = 0, a1 = 0;
#pragma unroll
            for (int i = 0; i < 8; i++) {
                ulonglong2 hv = hp[i];
                fma2(a0, w2[2 * i],     hv.x);
                fma2(a1, w2[2 * i + 1], hv.y);
            }
            asm("add.rn.f32x2 %0, %0, %1;" : "+l"(a0) : "l"(a1));
            uint32_t lo, hi;
            asm("mov.b64 {%0, %1}, %2;" : "=r"(lo), "=r"(hi) : "l"(a0));
            float acc = __uint_as_float(lo) + __uint_as_float(hi);

            // WAR guard: act warps must have read gate_p of step s-1
            if (s > 0) asm volatile("bar.sync 3, 576;" ::: "memory");
            gate_p[row * GPSTRIDE + ke] = acc + pr_cur;

            asm volatile("bar.arrive 1, 576;" ::: "memory");
            pr_cur = pr_nxt;
        }
    } else {
        // ================= act/send warps (16: units 0-7, 17: units 8-15) =================
        for (int s = 0; s < SEQ; s++) {
            const int cur = s & 1;
            const int nxt = cur ^ 1;
            const int t   = dir ? (SEQ - 1 - s) : s;
            asm volatile("bar.sync 1, 576;" ::: "memory");
            float hv = 0.f;
            if (l < 8) {
                int u = ubase + l;
                float gacc[4];
#pragma unroll
                for (int g = 0; g < 4; g++) {
                    const float* gp = &gate_p[(g * 16 + u) * GPSTRIDE];
                    float4 pA = *reinterpret_cast<const float4*>(gp);
                    float4 pB = *reinterpret_cast<const float4*>(gp + 4);
                    gacc[g] = ((pA.x + pA.y) + (pA.z + pA.w))
                            + ((pB.x + pB.y) + (pB.z + pB.w));
                }
                float gi = hsigmoid(gacc[0]);
                float gf = hsigmoid(gacc[1]);
                float gg = htanh(gacc[2]);
                float go = hsigmoid(gacc[3]);
                creg = gf * creg + gi * gg;
                hv = go * htanh(creg);
                stage[cur][u] = hv;
            }
            // done reading gate_p -> release the gemv warps' next write
            if (s != SEQ - 1) asm volatile("bar.arrive 3, 576;" ::: "memory");
            __syncwarp();
            if (s != SEQ - 1) {
                float4 v = reinterpret_cast<const float4*>(&stage[cur][0])[pkt];
                uint32_t ma = nxt ? ma1 : ma0;
                uint32_t dA = nxt ? d1 : d0;
                asm volatile(
                    "st.async.shared::cluster.mbarrier::complete_tx::bytes.v4.b32 [%0], {%1,%2,%3,%4}, [%5];"
                    :: "r"(dA), "r"(__float_as_uint(v.x)), "r"(__float_as_uint(v.y)),
                       "r"(__float_as_uint(v.z)), "r"(__float_as_uint(v.w)), "r"(ma) : "memory");
            }
            if (l < 8) hs[(size_t)t * HH + u0 + ubase + l] = hv;
        }
    }

    asm volatile("barrier.cluster.arrive.aligned;" ::: "memory");
    asm volatile("barrier.cluster.wait.aligned;"   ::: "memory");
}

// ---------------- kernel 3: feats = [hf|hb] @ W_out^T + b_out ----------------
__global__ void feats_kernel(const float* __restrict__ Wout, const float* __restrict__ bout) {
    int gid = blockIdx.x * 128 + threadIdx.x;     // grid 192 x 128 = 24576 exactly
    int t = gid / NTAGS, n = gid % NTAGS;
    const float4* hf = reinterpret_cast<const float4*>(g_hs + (size_t)t * HH);
    const float4* hb = reinterpret_cast<const float4*>(g_hs + (size_t)SEQ * HH + (size_t)t * HH);
    const float4* w0 = reinterpret_cast<const float4*>(Wout + (size_t)n * 512);
    const float4* w1 = reinterpret_cast<const float4*>(Wout + (size_t)n * 512 + 256);
    float acc = bout[n];
#pragma unroll 8
    for (int j = 0; j < 64; j++) {
        float4 a = hf[j], w = w0[j];
        acc = fmaf(a.x, w.x, fmaf(a.y, w.y, fmaf(a.z, w.z, fmaf(a.w, w.w, acc))));
    }
#pragma unroll 8
    for (int j = 0; j < 64; j++) {
        float4 a = hb[j], w = w1[j];
        acc = fmaf(a.x, w.x, fmaf(a.y, w.y, fmaf(a.z, w.z, fmaf(a.w, w.w, acc))));
    }
    g_feats[gid] = acc;
}

// ---------------- kernel 4a: per-chunk CRF transfer matrices ----------------
__global__ void crf_chunk_kernel(const float* __restrict__ trans) {
    const int c   = blockIdx.x;
    const int tid = threadIdx.x;          // < 144
    const int jo  = tid / NTAGS;
    const int ji  = tid % NTAGS;

    __shared__ float m_s[2][NTAGS][NTAGS];

    float tr[NTAGS];
#pragma unroll
    for (int p = 0; p < NTAGS; p++) tr[p] = trans[jo * NTAGS + p];

    float m = (jo == ji) ? 0.0f : NEGC;

    for (int step = 0; step < CLEN; step++) {
        int buf = step & 1;
        m_s[buf][jo][ji] = m;
        __syncthreads();
        float emit = g_feats[(c * CLEN + step) * NTAGS + jo];
        float mx = m_s[buf][0][ji] + tr[0];
#pragma unroll
        for (int p = 1; p < NTAGS; p++) mx = fmaxf(mx, m_s[buf][p][ji] + tr[p]);
        float ssum = 0.0f;
#pragma unroll
        for (int p = 0; p < NTAGS; p++) ssum += __expf(m_s[buf][p][ji] + tr[p] - mx);
        m = mx + __logf(ssum) + emit;
    }
    g_crfT[c][jo][ji] = m;
}

// ---------------- kernel 4b: fold chunk matrices + gold score -> loss ----------------
__global__ void crf_fold_kernel(const float* __restrict__ trans,
                                const int* __restrict__ tags,
                                float* __restrict__ out) {
    const int lane = threadIdx.x;
    float fv = (lane == TAG_START) ? 0.0f : NEGC;

    for (int c = 0; c < NCHUNK; c++) {
        float trow[NTAGS];
        if (lane < NTAGS) {
#pragma unroll
            for (int p = 0; p < NTAGS; p++) trow[p] = g_crfT[c][lane][p];
        } else {
#pragma unroll
            for (int p = 0; p < NTAGS; p++) trow[p] = NEGC;
        }
        float v[NTAGS];
#pragma unroll
        for (int p = 0; p < NTAGS; p++)
            v[p] = __shfl_sync(0xffffffffu, fv, p) + trow[p];
        float mx = v[0];
#pragma unroll
        for (int p = 1; p < NTAGS; p++) mx = fmaxf(mx, v[p]);
        float ssum = 0.0f;
#pragma unroll
        for (int p = 0; p < NTAGS; p++) ssum += __expf(v[p] - mx);
        float nf = mx + __logf(ssum);
        if (lane < NTAGS) fv = nf;
    }

    float sv = fv + ((lane < NTAGS) ? trans[TAG_STOP * NTAGS + lane] : 0.0f);
    float vv[NTAGS];
#pragma unroll
    for (int p = 0; p < NTAGS; p++)
        vv[p] = __shfl_sync(0xffffffffu, sv, p);
    float mx = vv[0];
#pragma unroll
    for (int p = 1; p < NTAGS; p++) mx = fmaxf(mx, vv[p]);
    float ssum = 0.0f;
#pragma unroll
    for (int p = 0; p < NTAGS; p++) ssum += __expf(vv[p] - mx);
    float fwd = mx + __logf(ssum);

    float gs = 0.0f;
    for (int t = lane; t < SEQ; t += 32) {
        int tg = tags[t];
        int pv = (t == 0) ? TAG_START : tags[t - 1];
        gs += trans[tg * NTAGS + pv] + g_feats[t * NTAGS + tg];
    }
#pragma unroll
    for (int o = 16; o; o >>= 1) gs += __shfl_xor_sync(0xffffffffu, gs, o);

    if (lane == 0) {
        gs += trans[TAG_STOP * NTAGS + tags[SEQ - 1]];
        out[0] = fwd - gs;
    }
}

// ---------------- launch ----------------
extern "C" void kernel_launch(void* const* d_in, const int* in_sizes, int n_in,
                              void* d_out, int out_size) {
    const int*   sent  = (const int*)  d_in[0];
    const int*   tags  = (const int*)  d_in[1];
    const float* embed = (const float*)d_in[2];
    const float* WihF  = (const float*)d_in[3];
    const float* WhhF  = (const float*)d_in[4];
    const float* bihF  = (const float*)d_in[5];
    const float* bhhF  = (const float*)d_in[6];
    const float* WihB  = (const float*)d_in[7];
    const float* WhhB  = (const float*)d_in[8];
    const float* bihB  = (const float*)d_in[9];
    const float* bhhB  = (const float*)d_in[10];
    const float* Wout  = (const float*)d_in[11];
    const float* bout  = (const float*)d_in[12];

    int iTrans = 15, iH0 = 13, iC0 = 14;
    if (in_sizes[13] == 144) { iTrans = 13; iH0 = 14; iC0 = 15; }
    const float* trans = (const float*)d_in[iTrans];
    const float* h0    = (const float*)d_in[iH0];
    const float* c0    = (const float*)d_in[iC0];

    float* out = (float*)d_out;

    // cluster size 16 > portable max 8: needs the nonportable attribute
    cudaFuncSetAttribute(lstm_rec_kernel,
                         cudaFuncAttributeNonPortableClusterSizeAllowed, 1);

    gather_x_kernel<<<SEQ, 64>>>(embed, sent);
    gemm_pre_kernel<<<dim3(8, 32, 2), 256>>>(WihF, WihB, bihF, bhhF, bihB, bhhB);
    dummy_kernel<<<1, 32>>>();   // launch-slot shim: keeps lstm_rec in ncu's capture slot
    lstm_rec_kernel<<<32, 576>>>(WhhF, WhhB, h0, c0);
    feats_kernel<<<192, 128>>>(Wout, bout);
    crf_chunk_kernel<<<NCHUNK, 144>>>(trans);
    crf_fold_kernel<<<1, 32>>>(trans, tags, out);
}

// round 15
// speedup vs baseline: 1.0707x; 1.0707x over previous
#include <cuda_runtime.h>
#include <cuda_bf16.h>
#include <cstdint>

#define SEQ    2048
#define EMB    256
#define HH     256
#define G4     1024      // 4*HH gate rows
#define NTAGS  12
#define TAG_START 10
#define TAG_STOP  11
#define NEGC  (-10000.0f)
#define NCHUNK 128
#define CLEN   (SEQ / NCHUNK)
#define CL     16                  // cluster size (CTAs per direction)
#define EPAD   36                  // padded eighth stride in floats (32 + 4)
#define HBUF8  (8 * EPAD)          // 288 floats per h buffer

// ---------------- scratch (device globals; no allocation allowed) ----------------
__device__ float g_xbuf[SEQ * EMB];            // gathered embeddings       (2 MB)
__device__ float g_pre [2 * SEQ * G4];         // input projections f/b     (16 MB)
__device__ float g_hs  [2 * SEQ * HH];         // hidden states f/b         (4 MB)
__device__ float g_feats[SEQ * NTAGS];         // emissions
__device__ float g_crfT[NCHUNK][NTAGS][NTAGS]; // per-chunk CRF transfer matrices
__device__ int   g_dummy;

__device__ __forceinline__ uint32_t smem_u32(const void* p) {
    return (uint32_t)__cvta_generic_to_shared(p);
}

__device__ __forceinline__ float htanh(float x) {
    float y;
    asm("tanh.approx.f32 %0, %1;" : "=f"(y) : "f"(x));
    return y;
}
__device__ __forceinline__ float hsigmoid(float x) {
    return fmaf(0.5f, htanh(0.5f * x), 0.5f);
}

__device__ __forceinline__ void fma2(unsigned long long& d,
                                     unsigned long long a, unsigned long long b) {
    asm("fma.rn.f32x2 %0, %1, %2, %0;" : "+l"(d) : "l"(a), "l"(b));
}

__device__ __forceinline__ void mbar_wait_acq(uint32_t mb, uint32_t parity) {
    uint32_t done;
    asm volatile(
        "{\n\t.reg .pred p;\n\t"
        "mbarrier.try_wait.parity.acquire.cluster.shared::cta.b64 p, [%1], %2, 0x989680;\n\t"
        "selp.b32 %0, 1, 0, p;\n\t}"
        : "=r"(done) : "r"(mb), "r"(parity) : "memory");
    while (!done) {
        asm volatile(
            "{\n\t.reg .pred p;\n\t"
            "mbarrier.try_wait.parity.acquire.cluster.shared::cta.b64 p, [%1], %2, 0x989680;\n\t"
            "selp.b32 %0, 1, 0, p;\n\t}"
            : "=r"(done) : "r"(mb), "r"(parity) : "memory");
    }
}

// ---------------- kernel 0: embedding gather ----------------
__global__ void gather_x_kernel(const float* __restrict__ embed,
                                const int* __restrict__ sent) {
    int t = blockIdx.x;
    int k = threadIdx.x;
    long row = (long)sent[t];
    float4 v = reinterpret_cast<const float4*>(embed + row * EMB)[k];
    reinterpret_cast<float4*>(g_xbuf + t * EMB)[k] = v;
}

// ---------------- kernel 1: pre = x @ Wih^T + bih + bhh (128x64 tiles, 8x4/thread) ----------------
__global__ void gemm_pre_kernel(const float* __restrict__ WihF, const float* __restrict__ WihB,
                                const float* __restrict__ bihF, const float* __restrict__ bhhF,
                                const float* __restrict__ bihB, const float* __restrict__ bhhB) {
    const int dir = blockIdx.z;
    const int r0  = blockIdx.x * 128;
    const int t0  = blockIdx.y * 64;
    const float* __restrict__ Wih = dir ? WihB : WihF;
    const float* __restrict__ bih = dir ? bihB : bihF;
    const float* __restrict__ bhh = dir ? bhhB : bhhF;

    __shared__ float Ws[32][128];   // [k][r swizzled by k4]
    __shared__ float Xs[32][68];    // [k][t] (+4 pad)

    const int tid = threadIdx.x;
    const int tx = tid & 15;
    const int ty = tid >> 4;
    float acc[8][4] = {};

    for (int kc = 0; kc < EMB; kc += 32) {
#pragma unroll
        for (int i = 0; i < 4; i++) {
            int s = tid + i * 256;
            int r = s >> 3, k4 = s & 7;
            float4 v = *reinterpret_cast<const float4*>(&Wih[(size_t)(r0 + r) * EMB + kc + k4 * 4]);
            int rs = r ^ (k4 << 3);
            Ws[k4 * 4 + 0][rs] = v.x;
            Ws[k4 * 4 + 1][rs] = v.y;
            Ws[k4 * 4 + 2][rs] = v.z;
            Ws[k4 * 4 + 3][rs] = v.w;
        }
#pragma unroll
        for (int i = 0; i < 2; i++) {
            int s = tid + i * 256;
            int t = s >> 3, k4 = s & 7;
            float4 v = *reinterpret_cast<const float4*>(&g_xbuf[(size_t)(t0 + t) * EMB + kc + k4 * 4]);
            Xs[k4 * 4 + 0][t] = v.x;
            Xs[k4 * 4 + 1][t] = v.y;
            Xs[k4 * 4 + 2][t] = v.z;
            Xs[k4 * 4 + 3][t] = v.w;
        }
        __syncthreads();
#pragma unroll
        for (int k = 0; k < 32; k++) {
            const int k4 = k >> 2;
            const int rbase = ((ty ^ k4) & 15) << 3;
            float4 wv0 = *reinterpret_cast<const float4*>(&Ws[k][rbase]);
            float4 wv1 = *reinterpret_cast<const float4*>(&Ws[k][rbase + 4]);
            float4 xv  = *reinterpret_cast<const float4*>(&Xs[k][tx << 2]);
            float wr[8] = {wv0.x, wv0.y, wv0.z, wv0.w, wv1.x, wv1.y, wv1.z, wv1.w};
            float xc[4] = {xv.x, xv.y, xv.z, xv.w};
#pragma unroll
            for (int i = 0; i < 8; i++)
#pragma unroll
                for (int j = 0; j < 4; j++)
                    acc[i][j] = fmaf(wr[i], xc[j], acc[i][j]);
        }
        __syncthreads();
    }
    float b[8];
#pragma unroll
    for (int i = 0; i < 8; i++) {
        int r = r0 + ty * 8 + i;
        b[i] = bih[r] + bhh[r];
    }
    float* preD = g_pre + (size_t)dir * SEQ * G4;
#pragma unroll
    for (int j = 0; j < 4; j++) {
        int t = t0 + tx * 4 + j;
        float4 v0, v1;
        v0.x = acc[0][j] + b[0];
        v0.y = acc[1][j] + b[1];
        v0.z = acc[2][j] + b[2];
        v0.w = acc[3][j] + b[3];
        v1.x = acc[4][j] + b[4];
        v1.y = acc[5][j] + b[5];
        v1.z = acc[6][j] + b[6];
        v1.w = acc[7][j] + b[7];
        float* dst = preD + (size_t)t * G4 + r0 + ty * 8;
        *reinterpret_cast<float4*>(dst)     = v0;
        *reinterpret_cast<float4*>(dst + 4) = v1;
    }
}

// ---------------- dummy kernel (launch-slot shim so ncu captures the lstm kernel) ----------------
__global__ void dummy_kernel() {
    if (threadIdx.x == 0) g_dummy = 1;
}

// ---------------- kernel 2: LSTM recurrence, 16-CTA cluster, QUARTER sub-barriers ----------------
// R13 structure (the 1249us champion) with one hardening change: gate_p is
// DOUBLE-BUFFERED by step parity, closing the WAR window where a gemv warp,
// released early by its quarter sub-mbar, could overwrite partials the local
// act warp had not yet read. Causality for same-parity reuse (s vs s+2):
// gemv(s+2) <- wait(s+2) <- remote sends(s+1) <- remote bar1(s+1)
// <- remote waits(s+1) <- OUR send(s) <- our act read of gate_p[cur] at s.
__global__ void __launch_bounds__(576, 1) __cluster_dims__(CL, 1, 1)
lstm_rec_kernel(const float* __restrict__ WhhF, const float* __restrict__ WhhB,
                const float* __restrict__ h0, const float* __restrict__ c0) {
    const int tid = threadIdx.x;
    const int w   = tid >> 5;
    const int l   = tid & 31;
    const int crank = blockIdx.x & (CL - 1);   // rank within cluster
    const int dir   = blockIdx.x >> 4;         // 0 = forward, 1 = backward
    const int u0    = crank * 16;              // first hidden unit owned by this CTA

    const float* __restrict__ Whh = dir ? WhhB : WhhF;
    const float* __restrict__ pre = g_pre + (size_t)dir * SEQ * G4;
    float* __restrict__ hs = g_hs + (size_t)dir * SEQ * HH;

    __shared__ __align__(16) float  hbuf[2][HBUF8];
    __shared__ __align__(16) float4 gate_p[2][64];   // [buf][row] = 4 quarter partials
    __shared__ __align__(16) float  stage[2][16];
    __shared__ __align__(8) unsigned long long mbarS[8];   // [kq*2 + buf]

    // init: every CTA loads the FULL initial h locally (eighth-padded layout)
    if (tid < HH) hbuf[0][(tid >> 5) * EPAD + (tid & 31)] = h0[dir * HH + tid];
    const int ubase = (w >= 16) ? (w - 16) * 8 : 0;
    float creg = 0.f;
    if (w >= 16 && l < 8) creg = c0[dir * HH + u0 + ubase + l];

    const uint32_t hbase = smem_u32(&hbuf[0][0]);
    const uint32_t mb0   = smem_u32(&mbarS[0]);
    const uint32_t mbDelta = mb0 - hbase;

    if (tid == 0) {
#pragma unroll
        for (int i = 0; i < 8; i++) {
            uint32_t a = mb0 + i * 8;
            asm volatile("mbarrier.init.shared.b64 [%0], 1;" :: "r"(a) : "memory");
            asm volatile("mbarrier.arrive.expect_tx.shared.b64 _, [%0], 256;" :: "r"(a) : "memory");
        }
    }

    // gemv mapping (warps 0-15): quarter kq = w>>2, gate = w&3, lane = (rowpair, half)
    const int kq   = w >> 2;
    const int gate = w & 3;
    const int urow = l >> 1;                  // unit index 0..15 within gate
    const int half = l & 1;                   // 32-float half of the 64-float quarter
    const int row  = gate * 16 + urow;        // local gate row 0..63
    const int ke   = kq * 2 + half;           // eighth index 0..7
    const int grow = gate * HH + u0 + urow;   // global gate row

    unsigned long long w2[16];
    if (w < 16) {
        const ulonglong2* wr = reinterpret_cast<const ulonglong2*>(Whh + (size_t)grow * HH + ke * 32);
#pragma unroll
        for (int i = 0; i < 8; i++) {
            ulonglong2 v = wr[i];
            w2[2 * i]     = v.x;
            w2[2 * i + 1] = v.y;
        }
    }

    // act/send warp addressing (warps 16,17): lane -> rank l&15, packet
    uint32_t ma0 = 0, ma1 = 0, d0 = 0, d1 = 0;
    int pkt = 0;
    if (w >= 16) {
        int s_rank = l & 15;
        pkt = (w - 16) * 2 + (l >> 4);        // 0..3: my slice's 16B packet index
        uint32_t pb;
        asm("mapa.shared::cluster.u32 %0, %1, %2;" : "=r"(pb) : "r"(hbase), "r"(s_rank));
        uint32_t dstOff = (uint32_t)(((crank >> 1) * EPAD + (crank & 1) * 16) * 4) + (uint32_t)pkt * 16;
        int q = crank >> 2;                   // which sub-mbar my data feeds
        ma0 = pb + mbDelta + (uint32_t)(q * 2 + 0) * 8;
        ma1 = pb + mbDelta + (uint32_t)(q * 2 + 1) * 8;
        d0  = pb + dstOff;
        d1  = pb + (uint32_t)(HBUF8 * 4) + dstOff;
    }
    __syncthreads();
    // mbarrier inits + phase-0 expects must be cluster-visible before any send
    asm volatile("barrier.cluster.arrive.aligned;" ::: "memory");
    asm volatile("barrier.cluster.wait.aligned;"   ::: "memory");

    if (w < 16) {
        // ================= gemv warps =================
        int pcq[2] = {0, 0};
        const bool hasPre   = (kq == 0) && (half == 0);
        const bool reposter = (gate == 0) && (l == 0);
        float pr_cur = 0.f;
        if (hasPre) pr_cur = __ldg(&pre[(size_t)(dir ? (SEQ - 1) : 0) * G4 + grow]);

        for (int s = 0; s < SEQ; s++) {
            const int cur = s & 1;
            float pr_nxt = 0.f;
            if (hasPre && s + 1 < SEQ) {
                int tn = dir ? (SEQ - 2 - s) : (s + 1);
                pr_nxt = __ldg(&pre[(size_t)tn * G4 + grow]);
            }

            if (s > 0) {
                uint32_t parity = (uint32_t)(pcq[cur] & 1);
                pcq[cur]++;
                uint32_t mb = mb0 + (uint32_t)(kq * 2 + cur) * 8;
                mbar_wait_acq(mb, parity);
                if (reposter)
                    asm volatile("mbarrier.arrive.expect_tx.shared.b64 _, [%0], 256;" :: "r"(mb) : "memory");
            }

            // ---- gemv: 32-wide eighth, linear conflict-free reads ----
            const ulonglong2* hp = reinterpret_cast<const ulonglong2*>(&hbuf[cur][ke * EPAD]);
            unsigned long long a0 = 0, a1 = 0;
#pragma unroll
            for (int i = 0; i < 8; i++) {
                ulonglong2 hv = hp[i];
                fma2(a0, w2[2 * i],     hv.x);
                fma2(a1, w2[2 * i + 1], hv.y);
            }
            asm("add.rn.f32x2 %0, %0, %1;" : "+l"(a0) : "l"(a1));
            uint32_t lo, hi;
            asm("mov.b64 {%0, %1}, %2;" : "=r"(lo), "=r"(hi) : "l"(a0));
            float acc = __uint_as_float(lo) + __uint_as_float(hi);
            acc += __shfl_xor_sync(0xffffffffu, acc, 1);   // combine halves
            if (half == 0)
                reinterpret_cast<float*>(&gate_p[cur][row])[kq] = acc + pr_cur;

            asm volatile("bar.arrive 1, 576;" ::: "memory");
            pr_cur = pr_nxt;
        }
    } else {
        // ================= act/send warps (16: units 0-7, 17: units 8-15) =================
        for (int s = 0; s < SEQ; s++) {
            const int cur = s & 1;
            const int nxt = cur ^ 1;
            const int t   = dir ? (SEQ - 1 - s) : s;
            asm volatile("bar.sync 1, 576;" ::: "memory");
            float hv = 0.f;
            if (l < 8) {
                int u = ubase + l;
                float4 p0 = gate_p[cur][u];          // gate i
                float4 p1 = gate_p[cur][16 + u];     // gate f
                float4 p2 = gate_p[cur][32 + u];     // gate g
                float4 p3 = gate_p[cur][48 + u];     // gate o
                float gi = (p0.x + p0.y) + (p0.z + p0.w);
                float gf = (p1.x + p1.y) + (p1.z + p1.w);
                float gg = (p2.x + p2.y) + (p2.z + p2.w);
                float go = (p3.x + p3.y) + (p3.z + p3.w);
                gi = hsigmoid(gi);
                gf = hsigmoid(gf);
                gg = htanh(gg);
                go = hsigmoid(go);
                creg = gf * creg + gi * gg;
                hv = go * htanh(creg);
                stage[cur][u] = hv;
            }
            __syncwarp();
            if (s != SEQ - 1) {
                float4 v = reinterpret_cast<const float4*>(&stage[cur][0])[pkt];
                uint32_t ma = nxt ? ma1 : ma0;
                uint32_t dA = nxt ? d1 : d0;
                asm volatile(
                    "st.async.shared::cluster.mbarrier::complete_tx::bytes.v4.b32 [%0], {%1,%2,%3,%4}, [%5];"
                    :: "r"(dA), "r"(__float_as_uint(v.x)), "r"(__float_as_uint(v.y)),
                       "r"(__float_as_uint(v.z)), "r"(__float_as_uint(v.w)), "r"(ma) : "memory");
            }
            if (l < 8) hs[(size_t)t * HH + u0 + ubase + l] = hv;
        }
    }

    asm volatile("barrier.cluster.arrive.aligned;" ::: "memory");
    asm volatile("barrier.cluster.wait.aligned;"   ::: "memory");
}

// ---------------- kernel 3: feats = [hf|hb] @ W_out^T + b_out ----------------
__global__ void feats_kernel(const float* __restrict__ Wout, const float* __restrict__ bout) {
    int gid = blockIdx.x * 128 + threadIdx.x;     // grid 192 x 128 = 24576 exactly
    int t = gid / NTAGS, n = gid % NTAGS;
    const float4* hf = reinterpret_cast<const float4*>(g_hs + (size_t)t * HH);
    const float4* hb = reinterpret_cast<const float4*>(g_hs + (size_t)SEQ * HH + (size_t)t * HH);
    const float4* w0 = reinterpret_cast<const float4*>(Wout + (size_t)n * 512);
    const float4* w1 = reinterpret_cast<const float4*>(Wout + (size_t)n * 512 + 256);
    float acc = bout[n];
#pragma unroll 8
    for (int j = 0; j < 64; j++) {
        float4 a = hf[j], w = w0[j];
        acc = fmaf(a.x, w.x, fmaf(a.y, w.y, fmaf(a.z, w.z, fmaf(a.w, w.w, acc))));
    }
#pragma unroll 8
    for (int j = 0; j < 64; j++) {
        float4 a = hb[j], w = w1[j];
        acc = fmaf(a.x, w.x, fmaf(a.y, w.y, fmaf(a.z, w.z, fmaf(a.w, w.w, acc))));
    }
    g_feats[gid] = acc;
}

// ---------------- kernel 4a: per-chunk CRF transfer matrices ----------------
__global__ void crf_chunk_kernel(const float* __restrict__ trans) {
    const int c   = blockIdx.x;
    const int tid = threadIdx.x;          // < 144
    const int jo  = tid / NTAGS;
    const int ji  = tid % NTAGS;

    __shared__ float m_s[2][NTAGS][NTAGS];

    float tr[NTAGS];
#pragma unroll
    for (int p = 0; p < NTAGS; p++) tr[p] = trans[jo * NTAGS + p];

    float m = (jo == ji) ? 0.0f : NEGC;

    for (int step = 0; step < CLEN; step++) {
        int buf = step & 1;
        m_s[buf][jo][ji] = m;
        __syncthreads();
        float emit = g_feats[(c * CLEN + step) * NTAGS + jo];
        float mx = m_s[buf][0][ji] + tr[0];
#pragma unroll
        for (int p = 1; p < NTAGS; p++) mx = fmaxf(mx, m_s[buf][p][ji] + tr[p]);
        float ssum = 0.0f;
#pragma unroll
        for (int p = 0; p < NTAGS; p++) ssum += __expf(m_s[buf][p][ji] + tr[p] - mx);
        m = mx + __logf(ssum) + emit;
    }
    g_crfT[c][jo][ji] = m;
}

// ---------------- kernel 4b: fold chunk matrices + gold score -> loss ----------------
__global__ void crf_fold_kernel(const float* __restrict__ trans,
                                const int* __restrict__ tags,
                                float* __restrict__ out) {
    const int lane = threadIdx.x;
    float fv = (lane == TAG_START) ? 0.0f : NEGC;

    for (int c = 0; c < NCHUNK; c++) {
        float trow[NTAGS];
        if (lane < NTAGS) {
#pragma unroll
            for (int p = 0; p < NTAGS; p++) trow[p] = g_crfT[c][lane][p];
        } else {
#pragma unroll
            for (int p = 0; p < NTAGS; p++) trow[p] = NEGC;
        }
        float v[NTAGS];
#pragma unroll
        for (int p = 0; p < NTAGS; p++)
            v[p] = __shfl_sync(0xffffffffu, fv, p) + trow[p];
        float mx = v[0];
#pragma unroll
        for (int p = 1; p < NTAGS; p++) mx = fmaxf(mx, v[p]);
        float ssum = 0.0f;
#pragma unroll
        for (int p = 0; p < NTAGS; p++) ssum += __expf(v[p] - mx);
        float nf = mx + __logf(ssum);
        if (lane < NTAGS) fv = nf;
    }

    float sv = fv + ((lane < NTAGS) ? trans[TAG_STOP * NTAGS + lane] : 0.0f);
    float vv[NTAGS];
#pragma unroll
    for (int p = 0; p < NTAGS; p++)
        vv[p] = __shfl_sync(0xffffffffu, sv, p);
    float mx = vv[0];
#pragma unroll
    for (int p = 1; p < NTAGS; p++) mx = fmaxf(mx, vv[p]);
    float ssum = 0.0f;
#pragma unroll
    for (int p = 0; p < NTAGS; p++) ssum += __expf(vv[p] - mx);
    float fwd = mx + __logf(ssum);

    float gs = 0.0f;
    for (int t = lane; t < SEQ; t += 32) {
        int tg = tags[t];
        int pv = (t == 0) ? TAG_START : tags[t - 1];
        gs += trans[tg * NTAGS + pv] + g_feats[t * NTAGS + tg];
    }
#pragma unroll
    for (int o = 16; o; o >>= 1) gs += __shfl_xor_sync(0xffffffffu, gs, o);

    if (lane == 0) {
        gs += trans[TAG_STOP * NTAGS + tags[SEQ - 1]];
        out[0] = fwd - gs;
    }
}

// ---------------- launch ----------------
extern "C" void kernel_launch(void* const* d_in, const int* in_sizes, int n_in,
                              void* d_out, int out_size) {
    const int*   sent  = (const int*)  d_in[0];
    const int*   tags  = (const int*)  d_in[1];
    const float* embed = (const float*)d_in[2];
    const float* WihF  = (const float*)d_in[3];
    const float* WhhF  = (const float*)d_in[4];
    const float* bihF  = (const float*)d_in[5];
    const float* bhhF  = (const float*)d_in[6];
    const float* WihB  = (const float*)d_in[7];
    const float* WhhB  = (const float*)d_in[8];
    const float* bihB  = (const float*)d_in[9];
    const float* bhhB  = (const float*)d_in[10];
    const float* Wout  = (const float*)d_in[11];
    const float* bout  = (const float*)d_in[12];

    int iTrans = 15, iH0 = 13, iC0 = 14;
    if (in_sizes[13] == 144) { iTrans = 13; iH0 = 14; iC0 = 15; }
    const float* trans = (const float*)d_in[iTrans];
    const float* h0    = (const float*)d_in[iH0];
    const float* c0    = (const float*)d_in[iC0];

    float* out = (float*)d_out;

    // cluster size 16 > portable max 8: needs the nonportable attribute
    cudaFuncSetAttribute(lstm_rec_kernel,
                         cudaFuncAttributeNonPortableClusterSizeAllowed, 1);

    gather_x_kernel<<<SEQ, 64>>>(embed, sent);
    gemm_pre_kernel<<<dim3(8, 32, 2), 256>>>(WihF, WihB, bihF, bhhF, bihB, bhhB);
    dummy_kernel<<<1, 32>>>();   // launch-slot shim: keeps lstm_rec in ncu's capture slot
    lstm_rec_kernel<<<32, 576>>>(WhhF, WhhB, h0, c0);
    feats_kernel<<<192, 128>>>(Wout, bout);
    crf_chunk_kernel<<<NCHUNK, 144>>>(trans);
    crf_fold_kernel<<<1, 32>>>(trans, tags, out);
}